// round 4
// baseline (speedup 1.0000x reference)
#include <cuda_runtime.h>

// ---------------- problem constants ----------------
#define HW    36864        // 192*192 detector pixels
#define NSUB  18432        // H*W/2
#define BATCH 2
#define NVOX  7077888      // 192^3
#define NV4   1769472      // NVOX/4
#define KCH   16           // alpha chunks (lanes) per ray

#define F_INF __int_as_float(0x7f800000)

// ---------------- device scratch (static, no allocations) ----------------
__device__ __align__(16) float g_density[NVOX];
__device__ float g_part[512 * 3];
__device__ float g_scalars[3];       // soft_min, dmin, inv_range
__device__ float g_pose[BATCH][16];  // R(9), source(3), t(3)

// ---------------- pass 1: partial reductions over volume ----------------
__global__ void k_reduce1(const float4* __restrict__ vol) {
    float smin = F_INF, omin = F_INF, omax = -F_INF;
    int stride = gridDim.x * blockDim.x;
    for (int i = blockIdx.x * blockDim.x + threadIdx.x; i < NV4; i += stride) {
        float4 v4 = vol[i];
        float vs[4] = {v4.x, v4.y, v4.z, v4.w};
        #pragma unroll
        for (int c = 0; c < 4; c++) {
            float v = vs[c];
            if (v > -800.0f) {
                omin = fminf(omin, v);
                omax = fmaxf(omax, v);
                if (v <= 350.0f) smin = fminf(smin, v);
            }
        }
    }
    __shared__ float s0[256], s1[256], s2[256];
    int t = threadIdx.x;
    s0[t] = smin; s1[t] = omin; s2[t] = omax;
    __syncthreads();
    for (int o = 128; o; o >>= 1) {
        if (t < o) {
            s0[t] = fminf(s0[t], s0[t + o]);
            s1[t] = fminf(s1[t], s1[t + o]);
            s2[t] = fmaxf(s2[t], s2[t + o]);
        }
        __syncthreads();
    }
    if (t == 0) {
        g_part[blockIdx.x * 3 + 0] = s0[0];
        g_part[blockIdx.x * 3 + 1] = s1[0];
        g_part[blockIdx.x * 3 + 2] = s2[0];
    }
}

// ---------------- pass 2: final reduction -> scalars ----------------
__global__ void k_reduce2() {
    __shared__ float s0[512], s1[512], s2[512];
    int t = threadIdx.x;
    s0[t] = g_part[t * 3 + 0];
    s1[t] = g_part[t * 3 + 1];
    s2[t] = g_part[t * 3 + 2];
    __syncthreads();
    for (int o = 256; o; o >>= 1) {
        if (t < o) {
            s0[t] = fminf(s0[t], s0[t + o]);
            s1[t] = fminf(s1[t], s1[t + o]);
            s2[t] = fmaxf(s2[t], s2[t + o]);
        }
        __syncthreads();
    }
    if (t == 0) {
        float smin = s0[0];
        float dmin = fminf(smin, s1[0]);
        float dmax = fmaxf(smin, s2[0]);
        g_scalars[0] = smin;
        g_scalars[1] = dmin;
        g_scalars[2] = 1.0f / (dmax - dmin);
    }
}

// ---------------- density fill: flip axis0 + normalize ----------------
__global__ void k_fill(const float4* __restrict__ vol) {
    float smin = g_scalars[0], dmin = g_scalars[1], inv = g_scalars[2];
    int stride = gridDim.x * blockDim.x;
    for (int j = blockIdx.x * blockDim.x + threadIdx.x; j < NV4; j += stride) {
        int e  = j << 2;
        int ix = e / HW;
        int rem = e - ix * HW;
        int sj = ((191 - ix) * HW + rem) >> 2;
        float4 v = vol[sj];
        float4 o;
        o.x = ((v.x <= -800.0f ? smin : v.x) - dmin) * inv;
        o.y = ((v.y <= -800.0f ? smin : v.y) - dmin) * inv;
        o.z = ((v.z <= -800.0f ? smin : v.z) - dmin) * inv;
        o.w = ((v.w <= -800.0f ? smin : v.w) - dmin) * inv;
        reinterpret_cast<float4*>(g_density)[j] = o;
    }
}

// ---------------- pose precompute: R = Rz@Ry@Rx, src, t ----------------
__global__ void k_pose(const float* __restrict__ rot, const float* __restrict__ tra) {
    int b = threadIdx.x;
    if (b >= BATCH) return;
    float cz, sz, cy, sy, cx, sx;
    sincosf(rot[b * 3 + 0], &sz, &cz);
    sincosf(rot[b * 3 + 1], &sy, &cy);
    sincosf(rot[b * 3 + 2], &sx, &cx);
    float R00 = cz * cy, R01 = -sz * cx + cz * sy * sx, R02 = sz * sx + cz * sy * cx;
    float R10 = sz * cy, R11 =  cz * cx + sz * sy * sx, R12 = -cz * sx + sz * sy * cx;
    float R20 = -sy,     R21 =  cy * sx,                R22 =  cy * cx;
    float tx = tra[b * 3 + 0] + 96.0f;
    float ty = tra[b * 3 + 1] + 96.0f;
    float tz = tra[b * 3 + 2] + 96.0f;
    float* P = g_pose[b];
    P[0] = R00; P[1] = R01; P[2] = R02;
    P[3] = R10; P[4] = R11; P[5] = R12;
    P[6] = R20; P[7] = R21; P[8] = R22;
    P[9]  = fmaf(R02, 300.0f, tx);   // source = R @ (0,0,300) + t
    P[10] = fmaf(R12, 300.0f, ty);
    P[11] = fmaf(R22, 300.0f, tz);
    P[12] = tx; P[13] = ty; P[14] = tz;
}

// ---------------- zero output ----------------
__global__ void k_zero(float* __restrict__ out, int n) {
    int i = blockIdx.x * blockDim.x + threadIdx.x;
    if (i < n) out[i] = 0.0f;
}

// Per-axis merge init at alpha=as.
//   al  : alpha of first plane crossing with al > as (INF if plane out of [0,192])
//   pf  : float plane index of that crossing (exact small integer)
//   di  : +1/-1 integer step
//   ci  : current cell index, derived from plane index (robust: a 1-ulp flip in
//         the plane decision corresponds to a ~zero-length segment, not a whole
//         chunk, unlike floor-of-midpoint).
__device__ __forceinline__ void ax_init(float as, float src, float sd, float ss, float iv,
                                        float& al, float& pf, int& di, int& ci) {
    bool pos = (ss > 0.0f);
    di = pos ? 1 : -1;
    float t = fmaf(as, sd, src);           // position along this axis at alpha=as
    int p;
    if (pos) { p = (int)floorf(t) + 1; if (p < 0)   p = 0;   }
    else     { p = (int)ceilf(t)  - 1; if (p > 192) p = 192; }
    pf = (float)p;
    al = (pf - src) * iv;
    if (al <= as) { p += di; pf = (float)p; al = (pf - src) * iv; }
    ci = pos ? (p - 1) : p;
    ci = min(191, max(0, ci));
    if (p < 0 || p > 192) al = F_INF;
}

// ---------------- raycast: KCH lanes per ray, exact-plane Siddon ----------------
__global__ void __launch_bounds__(256) k_ray(const int* __restrict__ sub, float* __restrict__ out) {
    int gtid  = blockIdx.x * 256 + threadIdx.x;
    int group = gtid >> 4;                 // ray id
    int lane  = gtid & (KCH - 1);
    int b = (group >= NSUB) ? 1 : 0;
    int n = group - b * NSUB;
    int pix = __ldg(&sub[n]);

    const float* P = g_pose[b];
    float R00 = P[0], R01 = P[1], R02 = P[2];
    float R10 = P[3], R11 = P[4], R12 = P[5];
    float R20 = P[6], R21 = P[7], R22 = P[8];
    float sx_ = P[9], sy_ = P[10], sz_ = P[11];
    float tx  = P[12], ty = P[13], tz = P[14];

    int piy  = pix / 192;
    int pixx = pix - piy * 192;
    float gx = ((float)pixx - 95.5f) * 2.0f;
    float gy = ((float)piy  - 95.5f) * 2.0f;
    const float gz = -300.0f;

    float tgx = fmaf(R02, gz, fmaf(R01, gy, R00 * gx)) + tx;
    float tgy = fmaf(R12, gz, fmaf(R11, gy, R10 * gx)) + ty;
    float tgz = fmaf(R22, gz, fmaf(R21, gy, R20 * gx)) + tz;

    float sdx = tgx - sx_, sdy = tgy - sy_, sdz = tgz - sz_;
    float ssx = (sdx == 0.0f) ? 1e-9f : sdx;
    float ssy = (sdy == 0.0f) ? 1e-9f : sdy;
    float ssz = (sdz == 0.0f) ? 1e-9f : sdz;
    float ivx = 1.0f / ssx, ivy = 1.0f / ssy, ivz = 1.0f / ssz;

    float ax0 = (0.0f   - sx_) * ivx, ax1 = (192.0f - sx_) * ivx;
    float ay0 = (0.0f   - sy_) * ivy, ay1 = (192.0f - sy_) * ivy;
    float az0 = (0.0f   - sz_) * ivz, az1 = (192.0f - sz_) * ivz;

    float amin = fmaxf(fmaxf(fminf(ax0, ax1), fminf(ay0, ay1)), fminf(az0, az1));
    amin = fmaxf(amin, 0.0f);
    float amax = fminf(fminf(fmaxf(ax0, ax1), fmaxf(ay0, ay1)), fmaxf(az0, az1));
    amax = fminf(amax, 1.0f);
    amax = fmaxf(amax, amin);

    float rl = sqrtf(fmaf(sdx, sdx, fmaf(sdy, sdy, sdz * sdz)));
    float da = (amax - amin) * (1.0f / (float)KCH);
    float as = fmaf((float)lane, da, amin);
    float ae = (lane == KCH - 1) ? amax : fmaf((float)(lane + 1), da, amin);

    float acc = 0.0f;
    if (ae > as) {
        float alx, aly, alz, pfx, pfy, pfz;
        int dix, diy, diz, cxi, cyi, czi;
        ax_init(as, sx_, sdx, ssx, ivx, alx, pfx, dix, cxi);
        ax_init(as, sy_, sdy, ssy, ivy, aly, pfy, diy, cyi);
        ax_init(as, sz_, sdz, ssz, ivz, alz, pfz, diz, czi);
        float dfx = (float)dix, dfy = (float)diy, dfz = (float)diz;

        float cur = fminf(alx, fminf(aly, alz));
        float prev = as;
        while (true) {
            float cseg = fminf(cur, ae);
            float vox = __ldg(&g_density[(cxi * 192 + cyi) * 192 + czi]);
            acc = fmaf(cseg - prev, vox, acc);
            if (cur >= ae) break;
            prev = cur;
            if (alx <= aly && alx <= alz) {
                pfx += dfx;
                cxi = min(191, max(0, cxi + dix));
                alx = (pfx < 0.0f || pfx > 192.0f) ? F_INF : (pfx - sx_) * ivx;
            } else if (aly <= alz) {
                pfy += dfy;
                cyi = min(191, max(0, cyi + diy));
                aly = (pfy < 0.0f || pfy > 192.0f) ? F_INF : (pfy - sy_) * ivy;
            } else {
                pfz += dfz;
                czi = min(191, max(0, czi + diz));
                alz = (pfz < 0.0f || pfz > 192.0f) ? F_INF : (pfz - sz_) * ivz;
            }
            cur = fminf(alx, fminf(aly, alz));
        }
    }
    acc *= rl;
    #pragma unroll
    for (int o = KCH / 2; o; o >>= 1)
        acc += __shfl_xor_sync(0xffffffffu, acc, o);
    if (lane == 0) out[b * HW + pix] = acc;
}

// ---------------- launch ----------------
extern "C" void kernel_launch(void* const* d_in, const int* in_sizes, int n_in,
                              void* d_out, int out_size) {
    const float* vol = (const float*)d_in[0];
    const float* rot = (const float*)d_in[1];
    const float* tra = (const float*)d_in[2];
    const int*   sub = (const int*)d_in[3];
    float* out = (float*)d_out;

    k_reduce1<<<512, 256>>>((const float4*)vol);
    k_reduce2<<<1, 512>>>();
    k_fill<<<6912, 256>>>((const float4*)vol);
    k_pose<<<1, 32>>>(rot, tra);
    k_zero<<<(HW * BATCH + 255) / 256, 256>>>(out, out_size);
    k_ray<<<(BATCH * NSUB * KCH) / 256, 256>>>(sub, out);
}